// round 4
// baseline (speedup 1.0000x reference)
#include <cuda_runtime.h>
#include <cstdint>
#include <cstddef>

#define D        128
#define DOUT     64
#define NN_MAX   100000
#define NE_MAX   1600000
#define L_MAX    3

// ---------------- scratch (static device globals; no allocation) ----------------
__device__ __align__(256) float g_agg [(size_t)NN_MAX * D];
__device__ __align__(256) float g_buf0[(size_t)NN_MAX * D];
__device__ __align__(256) float g_buf1[(size_t)NN_MAX * D];
__device__ __align__(256) float g_W2  [(size_t)L_MAX * 2 * D * D];   // per layer: [256][128], k-major
__device__ __align__(256) float g_fcT [(size_t)D * DOUT];            // [128][64], k-major
__device__ __align__(256) int   g_src [NE_MAX];
__device__ __align__(256) int   g_dst [NE_MAX];
__device__ int g_is64;

// ---------------- f32x2 packed-FMA helpers (Blackwell FFMA2) ----------------
__device__ __forceinline__ unsigned long long pack2(float lo, float hi) {
    unsigned long long r;
    asm("mov.b64 %0, {%1, %2};" : "=l"(r) : "f"(lo), "f"(hi));
    return r;
}
__device__ __forceinline__ void unpack2(unsigned long long v, float& lo, float& hi) {
    asm("mov.b64 {%0, %1}, %2;" : "=f"(lo), "=f"(hi) : "l"(v));
}
__device__ __forceinline__ void fma2(unsigned long long& acc, unsigned long long a,
                                     unsigned long long b) {
    asm("fma.rn.f32x2 %0, %1, %2, %0;" : "+l"(acc) : "l"(a), "l"(b));
}

// ---------------- edge-index width detection ----------------
// If edge_index is int64 (nonneg values < 2^31), every odd 32-bit word is 0.
// If it's int32, odd words are node ids (~1e-5 chance of any one being 0).
__global__ void k_detect(const int* __restrict__ ei32, int n32) {
    __shared__ int any;
    if (threadIdx.x == 0) any = 0;
    __syncthreads();
    int nsamp = 2048;
    for (int i = threadIdx.x; i < nsamp; i += blockDim.x) {
        int idx = 2 * i + 1;
        if (idx < n32 && ei32[idx] != 0) any = 1;
    }
    __syncthreads();
    if (threadIdx.x == 0) g_is64 = (any == 0) ? 1 : 0;
}

__global__ void k_prep_edges(const int* __restrict__ ei32, int nE, int M) {
    int i = blockIdx.x * blockDim.x + threadIdx.x;
    if (i >= nE) return;
    int s, d;
    if (g_is64) {
        const long long* e = (const long long*)ei32;
        s = (int)e[i];
        d = (int)e[i + (size_t)nE];
    } else {
        s = ei32[i];
        d = ei32[i + (size_t)nE];
    }
    // defensive clamp: never crash on a bad decode
    if (s < 0) s = 0; if (s >= M) s = M - 1;
    if (d < 0) d = 0; if (d >= M) d = M - 1;
    g_src[i] = s;
    g_dst[i] = d;
}

// g_W2[l][k][n] = (k<128 ? W_rel[l][n][k] : W_root[l][n][k-128]);  g_fcT[k][n] = fc_w[n][k]
__global__ void k_prep_w(const float* __restrict__ W_rel, const float* __restrict__ W_root,
                         const float* __restrict__ fc_w, int L) {
    int i = blockIdx.x * blockDim.x + threadIdx.x;
    int tot = L * 2 * D * D;
    if (i < tot) {
        int l = i / (2 * D * D);
        int r = i % (2 * D * D);
        int k = r / D;
        int n = r % D;
        float v = (k < D) ? W_rel[(size_t)l * D * D + n * D + k]
                          : W_root[(size_t)l * D * D + n * D + (k - D)];
        g_W2[i] = v;
    } else if (i < tot + D * DOUT) {
        int j = i - tot;
        int k = j / DOUT;
        int n = j % DOUT;
        g_fcT[j] = fc_w[(size_t)n * D + k];
    }
}

__global__ void k_zero4(float4* __restrict__ p, size_t n4) {
    size_t i = (size_t)blockIdx.x * blockDim.x + threadIdx.x;
    if (i < n4) p[i] = make_float4(0.f, 0.f, 0.f, 0.f);
}

// ---------------- edge scatter: warp per edge, vector reduction ----------------
__global__ void k_scatter(const float* __restrict__ x, float* __restrict__ agg, int nE) {
    int w = (int)(((size_t)blockIdx.x * blockDim.x + threadIdx.x) >> 5);
    int lane = threadIdx.x & 31;
    if (w >= nE) return;
    int s = g_src[w];
    int d = g_dst[w];
    float4 v = *(const float4*)(x + (size_t)s * D + lane * 4);
    float* ap = agg + (size_t)d * D + lane * 4;
    asm volatile("red.global.add.v4.f32 [%0], {%1, %2, %3, %4};"
                 :: "l"(ap), "f"(v.x), "f"(v.y), "f"(v.z), "f"(v.w) : "memory");
}

// ---------------- layer GEMM: C[M,128] = [agg|x][M,256] @ W2[256,128] + bias ----------------
// BM=128, BN=128, BK=8, 256 threads, thread tile 8x8, f32x2 accumulators,
// 1-deep global->reg prefetch pipeline.
__global__ __launch_bounds__(256, 2) void k_gemm_layer(
    const float* __restrict__ Aagg, const float* __restrict__ Ax,
    const float* __restrict__ W2, const float* __restrict__ bias,
    float* __restrict__ C, int M)
{
    __shared__ float As[8][128];
    __shared__ float Bs[8][128];

    const int tid  = threadIdx.x;
    const int trow = tid >> 4;          // 0..15  -> rows trow*8 .. +7
    const int tcol = tid & 15;          // 0..15  -> cols tcol*8 .. +7
    const int block_row = blockIdx.x * 128;

    // loader coords
    const int arow = tid >> 1;          // 0..127
    const int akk  = (tid & 1) << 2;    // 0 or 4
    const int bk   = tid >> 5;          // 0..7
    const int bn   = (tid & 31) << 2;   // 0..124

    int grow = block_row + arow;
    if (grow >= M) grow = M - 1;

    unsigned long long acc[8][4];
#pragma unroll
    for (int i = 0; i < 8; i++)
#pragma unroll
        for (int j = 0; j < 4; j++) acc[i][j] = 0ull;

    // prefetch slab 0
    float4 aref = *(const float4*)(Aagg + (size_t)grow * D + akk);
    float4 bref = *(const float4*)(W2 + (size_t)bk * D + bn);

#pragma unroll 1
    for (int s = 0; s < 32; ++s) {
        As[akk + 0][arow] = aref.x;
        As[akk + 1][arow] = aref.y;
        As[akk + 2][arow] = aref.z;
        As[akk + 3][arow] = aref.w;
        *(float4*)&Bs[bk][bn] = bref;
        __syncthreads();

        if (s + 1 < 32) {
            int k0 = (s + 1) * 8;
            const float* An = (k0 < D) ? Aagg : Ax;
            int kb = k0 & (D - 1);
            aref = *(const float4*)(An + (size_t)grow * D + kb + akk);
            bref = *(const float4*)(W2 + (size_t)(k0 + bk) * D + bn);
        }

#pragma unroll
        for (int k = 0; k < 8; ++k) {
            float4 a0 = *(const float4*)&As[k][trow * 8];
            float4 a1 = *(const float4*)&As[k][trow * 8 + 4];
            float4 b0 = *(const float4*)&Bs[k][tcol * 8];
            float4 b1 = *(const float4*)&Bs[k][tcol * 8 + 4];
            unsigned long long bb0 = pack2(b0.x, b0.y);
            unsigned long long bb1 = pack2(b0.z, b0.w);
            unsigned long long bb2 = pack2(b1.x, b1.y);
            unsigned long long bb3 = pack2(b1.z, b1.w);
            float av[8] = {a0.x, a0.y, a0.z, a0.w, a1.x, a1.y, a1.z, a1.w};
#pragma unroll
            for (int i = 0; i < 8; ++i) {
                unsigned long long aa = pack2(av[i], av[i]);
                fma2(acc[i][0], aa, bb0);
                fma2(acc[i][1], aa, bb1);
                fma2(acc[i][2], aa, bb2);
                fma2(acc[i][3], aa, bb3);
            }
        }
        __syncthreads();
    }

#pragma unroll
    for (int i = 0; i < 8; ++i) {
        int row = block_row + trow * 8 + i;
        if (row < M) {
            float* cp = C + (size_t)row * D + tcol * 8;
#pragma unroll
            for (int j = 0; j < 4; ++j) {
                float lo, hi;
                unpack2(acc[i][j], lo, hi);
                cp[2 * j + 0] = lo + bias[tcol * 8 + 2 * j + 0];
                cp[2 * j + 1] = hi + bias[tcol * 8 + 2 * j + 1];
            }
        }
    }
}

// ---------------- final GEMM: out[M,64] = A[M,128] @ fcT[128,64] + fc_b ----------------
// BM=128, BN=64, full-K B in smem, 256 threads, thread tile 8x4.
__global__ __launch_bounds__(256, 2) void k_gemm_final(
    const float* __restrict__ A, const float* __restrict__ fcT,
    const float* __restrict__ fcb, float* __restrict__ C, int M)
{
    __shared__ float Bs[D * DOUT];   // [128][64], 32 KB
    __shared__ float As[8][128];

    const int tid  = threadIdx.x;
    const int trow = tid >> 4;        // 0..15 -> rows trow*8 .. +7
    const int tcol = tid & 15;        // 0..15 -> cols tcol*4 .. +3
    const int block_row = blockIdx.x * 128;

    // load full B to shared (8192 floats, 8 float4 per thread, coalesced)
#pragma unroll
    for (int v = 0; v < 8; ++v) {
        int o = v * 1024 + tid * 4;
        *(float4*)&Bs[o] = *(const float4*)&fcT[o];
    }

    const int arow = tid >> 1;
    const int akk  = (tid & 1) << 2;
    int grow = block_row + arow;
    if (grow >= M) grow = M - 1;

    unsigned long long acc[8][2];
#pragma unroll
    for (int i = 0; i < 8; i++) { acc[i][0] = 0ull; acc[i][1] = 0ull; }

    float4 aref = *(const float4*)(A + (size_t)grow * D + akk);
    __syncthreads();   // Bs ready

#pragma unroll 1
    for (int s = 0; s < 16; ++s) {
        As[akk + 0][arow] = aref.x;
        As[akk + 1][arow] = aref.y;
        As[akk + 2][arow] = aref.z;
        As[akk + 3][arow] = aref.w;
        __syncthreads();

        if (s + 1 < 16) {
            int kb = (s + 1) * 8;
            aref = *(const float4*)(A + (size_t)grow * D + kb + akk);
        }

        int k0 = s * 8;
#pragma unroll
        for (int k = 0; k < 8; ++k) {
            float4 a0 = *(const float4*)&As[k][trow * 8];
            float4 a1 = *(const float4*)&As[k][trow * 8 + 4];
            float4 b  = *(const float4*)&Bs[(k0 + k) * DOUT + tcol * 4];
            unsigned long long bb0 = pack2(b.x, b.y);
            unsigned long long bb1 = pack2(b.z, b.w);
            float av[8] = {a0.x, a0.y, a0.z, a0.w, a1.x, a1.y, a1.z, a1.w};
#pragma unroll
            for (int i = 0; i < 8; ++i) {
                unsigned long long aa = pack2(av[i], av[i]);
                fma2(acc[i][0], aa, bb0);
                fma2(acc[i][1], aa, bb1);
            }
        }
        __syncthreads();
    }

#pragma unroll
    for (int i = 0; i < 8; ++i) {
        int row = block_row + trow * 8 + i;
        if (row < M) {
            float* cp = C + (size_t)row * DOUT + tcol * 4;
            float l0, h0, l1, h1;
            unpack2(acc[i][0], l0, h0);
            unpack2(acc[i][1], l1, h1);
            cp[0] = l0 + fcb[tcol * 4 + 0];
            cp[1] = h0 + fcb[tcol * 4 + 1];
            cp[2] = l1 + fcb[tcol * 4 + 2];
            cp[3] = h1 + fcb[tcol * 4 + 3];
        }
    }
}

// ---------------- host orchestration ----------------
extern "C" void kernel_launch(void* const* d_in, const int* in_sizes, int n_in,
                              void* d_out, int out_size)
{
    const float* x      = (const float*)d_in[0];
    const int*   ei32   = (const int*)d_in[1];     // width detected on-device
    const float* W_rel  = (const float*)d_in[2];
    const float* b_rel  = (const float*)d_in[3];
    const float* W_root = (const float*)d_in[4];
    const float* fc_w   = (const float*)d_in[5];
    const float* fc_b   = (const float*)d_in[6];
    float*       out    = (float*)d_out;

    int M  = in_sizes[0] / D;           // 100000
    int nE = in_sizes[1] / 2;           // 1600000
    int L  = in_sizes[2] / (D * D);     // 3
    if (M > NN_MAX) M = NN_MAX;
    if (nE > NE_MAX) nE = NE_MAX;
    if (L > L_MAX) L = L_MAX;

    float *agg, *buf0, *buf1, *W2, *fcT;
    cudaGetSymbolAddress((void**)&agg,  g_agg);
    cudaGetSymbolAddress((void**)&buf0, g_buf0);
    cudaGetSymbolAddress((void**)&buf1, g_buf1);
    cudaGetSymbolAddress((void**)&W2,   g_W2);
    cudaGetSymbolAddress((void**)&fcT,  g_fcT);

    k_detect<<<1, 256>>>(ei32, in_sizes[1]);
    k_prep_edges<<<(nE + 255) / 256, 256>>>(ei32, nE, M);
    int prep_tot = L * 2 * D * D + D * DOUT;
    k_prep_w<<<(prep_tot + 255) / 256, 256>>>(W_rel, W_root, fc_w, L);

    const float* cur = x;
    float* nxt = buf0;
    size_t n4 = (size_t)M * D / 4;
    int gemm_blocks = (M + 127) / 128;
    int scat_blocks = (nE + 7) / 8;      // warp per edge, 8 warps per block

    for (int l = 0; l < L; ++l) {
        k_zero4<<<(int)((n4 + 255) / 256), 256>>>((float4*)agg, n4);
        k_scatter<<<scat_blocks, 256>>>(cur, agg, nE);
        k_gemm_layer<<<gemm_blocks, 256>>>(agg, cur,
                                           W2 + (size_t)l * 2 * D * D,
                                           b_rel + (size_t)l * D,
                                           nxt, M);
        cur = nxt;
        nxt = (nxt == buf0) ? buf1 : buf0;
    }

    k_gemm_final<<<gemm_blocks, 256>>>(cur, fcT, fc_b, out, M);
}

// round 5
// speedup vs baseline: 1.0649x; 1.0649x over previous
#include <cuda_runtime.h>
#include <cstdint>
#include <cstddef>

#define D        128
#define DOUT     64
#define NN_MAX   100000
#define NE_MAX   1600000
#define L_MAX    3
#define KMAX     (L_MAX + 1)

// ---------------- scratch (static device globals; no allocation) ----------------
__device__ __align__(256) float g_V [L_MAX][(size_t)NN_MAX * DOUT]; // Horner buffers V1..V3
__device__ __align__(256) float g_d1[NN_MAX];                       // indegree  (A·1)
__device__ __align__(256) float g_d2[NN_MAX];                       // A·indegree
__device__ __align__(256) float g_Ma[KMAX][D * D];                  // M recurrence dbl-buffer
__device__ __align__(256) float g_Mb[KMAX][D * D];
__device__ __align__(256) float g_bA[KMAX][D];                      // beta dbl-buffer
__device__ __align__(256) float g_bB[KMAX][D];
__device__ __align__(256) float g_C [KMAX][D * DOUT];               // C_k[p][n], p-major
__device__ __align__(256) float g_gc[DOUT];                         // gamma0 + fc_b
__device__ __align__(256) float g_g1[DOUT];
__device__ __align__(256) float g_g2[DOUT];
__device__ __align__(256) int   g_src[NE_MAX];
__device__ __align__(256) int   g_dst[NE_MAX];
__device__ int g_is64;

// ---------------- f32x2 packed-FMA helpers (Blackwell FFMA2) ----------------
__device__ __forceinline__ unsigned long long pack2(float lo, float hi) {
    unsigned long long r;
    asm("mov.b64 %0, {%1, %2};" : "=l"(r) : "f"(lo), "f"(hi));
    return r;
}
__device__ __forceinline__ void unpack2(unsigned long long v, float& lo, float& hi) {
    asm("mov.b64 {%0, %1}, %2;" : "=f"(lo), "=f"(hi) : "l"(v));
}
__device__ __forceinline__ void fma2(unsigned long long& acc, unsigned long long a,
                                     unsigned long long b) {
    asm("fma.rn.f32x2 %0, %1, %2, %0;" : "+l"(acc) : "l"(a), "l"(b));
}

// ---------------- edge-index width detection (int64 vs int32) ----------------
__global__ void k_detect(const int* __restrict__ ei32, int n32) {
    __shared__ int any;
    if (threadIdx.x == 0) any = 0;
    __syncthreads();
    for (int i = threadIdx.x; i < 2048; i += blockDim.x) {
        int idx = 2 * i + 1;
        if (idx < n32 && ei32[idx] != 0) any = 1;
    }
    __syncthreads();
    if (threadIdx.x == 0) g_is64 = (any == 0) ? 1 : 0;
}

__global__ void k_prep_edges(const int* __restrict__ ei32, int nE, int M) {
    int i = blockIdx.x * blockDim.x + threadIdx.x;
    if (i >= nE) return;
    int s, d;
    if (g_is64) {
        const long long* e = (const long long*)ei32;
        s = (int)e[i];
        d = (int)e[i + (size_t)nE];
    } else {
        s = ei32[i];
        d = ei32[i + (size_t)nE];
    }
    if (s < 0) s = 0; if (s >= M) s = M - 1;
    if (d < 0) d = 0; if (d >= M) d = M - 1;
    g_src[i] = s;
    g_dst[i] = d;
}

// ---------------- tiny weight-recurrence precompute ----------------
// M_{0,0} = I; beta_0 = 0
__global__ void k_init_M() {
    int i = blockIdx.x * blockDim.x + threadIdx.x;
    int tot = KMAX * D * D;
    if (i < tot) {
        int k = i / (D * D);
        int r = i % (D * D);
        ((float*)g_Ma)[i] = (k == 0 && (r / D) == (r % D)) ? 1.f : 0.f;
    } else if (i < tot + KMAX * D) {
        ((float*)g_bA)[i - tot] = 0.f;
    }
}

// Stage l (1-based): Mout_k = Min_{k-1} @ Wr^T + Min_k @ Wt^T, inputs valid k' in [0, l-1].
// grid (4 row-tiles, l+1 k-values), 256 threads.
__global__ void k_stage(const float* __restrict__ Min, float* __restrict__ Mout,
                        const float* __restrict__ Wr, const float* __restrict__ Wt, int l) {
    __shared__ float sT[32][D];   // Min_k    (Wt term)
    __shared__ float sR[32][D];   // Min_{k-1}(Wr term)
    int k  = blockIdx.y;
    int p0 = blockIdx.x * 32;
    int tid = threadIdx.x;
    for (int i = tid; i < 32 * D; i += 256) {
        int p = i >> 7, q = i & 127;
        sT[p][q] = (k <= l - 1) ? Min[(size_t)k * D * D + (p0 + p) * D + q] : 0.f;
        sR[p][q] = (k >= 1)     ? Min[(size_t)(k - 1) * D * D + (p0 + p) * D + q] : 0.f;
    }
    __syncthreads();
    int p  = tid >> 3;
    int nb = (tid & 7) * 16;
    for (int n = nb; n < nb + 16; ++n) {
        float acc = 0.f;
        for (int q = 0; q < D; ++q)
            acc += sT[p][q] * Wt[n * D + q] + sR[p][q] * Wr[n * D + q];
        Mout[(size_t)k * D * D + (p0 + p) * D + n] = acc;
    }
}

// beta_out_k = Wr @ beta_in_{k-1} + Wt @ beta_in_k (+ b_l if k==0); inputs valid [0, l-2].
__global__ void k_stage_beta(const float* __restrict__ bin, float* __restrict__ bout,
                             const float* __restrict__ Wr, const float* __restrict__ Wt,
                             const float* __restrict__ bl, int l) {
    int n = threadIdx.x;
    for (int k = 0; k < l; ++k) {
        float acc = (k == 0) ? bl[n] : 0.f;
        for (int q = 0; q < D; ++q) {
            float t = (k <= l - 2) ? bin[k * D + q] : 0.f;
            float r = (k >= 1)     ? bin[(k - 1) * D + q] : 0.f;
            acc += Wt[n * D + q] * t + Wr[n * D + q] * r;
        }
        bout[k * D + n] = acc;
    }
}

// C_k[p][n] = sum_q M3_k[p][q] * fc_w[n][q]     grid (4, L+1)
__global__ void k_make_C(const float* __restrict__ M3, const float* __restrict__ fcw) {
    __shared__ float sM[32][D];
    int k  = blockIdx.y;
    int p0 = blockIdx.x * 32;
    int tid = threadIdx.x;
    for (int i = tid; i < 32 * D; i += 256) {
        int p = i >> 7, q = i & 127;
        sM[p][q] = M3[(size_t)k * D * D + (p0 + p) * D + q];
    }
    __syncthreads();
    int p  = tid >> 3;
    int nb = (tid & 7) * 8;
    for (int n = nb; n < nb + 8; ++n) {
        float acc = 0.f;
        for (int q = 0; q < D; ++q) acc += sM[p][q] * fcw[n * D + q];
        g_C[k][(p0 + p) * DOUT + n] = acc;
    }
}

__global__ void k_make_gamma(const float* __restrict__ b3, const float* __restrict__ fcw,
                             const float* __restrict__ fcb, int L) {
    int n = threadIdx.x;   // 0..63
    float a0 = fcb[n], a1 = 0.f, a2 = 0.f;
    for (int q = 0; q < D; ++q) {
        float w = fcw[n * D + q];
        a0 += w * b3[0 * D + q];
        if (L >= 2) a1 += w * b3[1 * D + q];
        if (L >= 3) a2 += w * b3[2 * D + q];
    }
    g_gc[n] = a0; g_g1[n] = a1; g_g2[n] = a2;
}

// ---------------- degree vectors ----------------
__global__ void k_zero_d(int M) {
    int i = blockIdx.x * blockDim.x + threadIdx.x;
    if (i < M) { g_d1[i] = 0.f; g_d2[i] = 0.f; }
}
__global__ void k_deg1(int nE) {
    int i = blockIdx.x * blockDim.x + threadIdx.x;
    if (i < nE) {
        float* p = &g_d1[g_dst[i]];
        asm volatile("red.global.add.f32 [%0], %1;" :: "l"(p), "f"(1.0f) : "memory");
    }
}
__global__ void k_deg2(int nE) {
    int i = blockIdx.x * blockDim.x + threadIdx.x;
    if (i < nE) {
        float v = g_d1[g_src[i]];
        float* p = &g_d2[g_dst[i]];
        asm volatile("red.global.add.f32 [%0], %1;" :: "l"(p), "f"(v) : "memory");
    }
}

// ---------------- projection GEMM: V_k = x0 @ C_k (+ bias terms for k==0) ----------------
// BM=128, BN=64, full-K B in smem, 256 threads, thread tile 8x4. grid (tiles, L+1).
__global__ __launch_bounds__(256, 2) void k_gemm_proj(
    const float* __restrict__ A, const float* __restrict__ d1,
    const float* __restrict__ d2, float* __restrict__ out, int M)
{
    __shared__ float Bs[D * DOUT];   // 32 KB
    __shared__ float As[8][128];

    const int kk = blockIdx.y;
    float* O = (kk == 0) ? out : &g_V[kk - 1][0];
    const float* B = &g_C[kk][0];

    const int tid  = threadIdx.x;
    const int trow = tid >> 4;
    const int tcol = tid & 15;
    const int block_row = blockIdx.x * 128;

#pragma unroll
    for (int v = 0; v < 8; ++v) {
        int o = v * 1024 + tid * 4;
        *(float4*)&Bs[o] = *(const float4*)&B[o];
    }

    const int arow = tid >> 1;
    const int akk  = (tid & 1) << 2;
    int grow = block_row + arow;
    if (grow >= M) grow = M - 1;

    unsigned long long acc[8][2];
#pragma unroll
    for (int i = 0; i < 8; i++) { acc[i][0] = 0ull; acc[i][1] = 0ull; }

    float4 aref = *(const float4*)(A + (size_t)grow * D + akk);
    __syncthreads();

#pragma unroll 1
    for (int s = 0; s < 16; ++s) {
        As[akk + 0][arow] = aref.x;
        As[akk + 1][arow] = aref.y;
        As[akk + 2][arow] = aref.z;
        As[akk + 3][arow] = aref.w;
        __syncthreads();

        if (s + 1 < 16) {
            int kb = (s + 1) * 8;
            aref = *(const float4*)(A + (size_t)grow * D + kb + akk);
        }

        int k0 = s * 8;
#pragma unroll
        for (int k = 0; k < 8; ++k) {
            float4 a0 = *(const float4*)&As[k][trow * 8];
            float4 a1 = *(const float4*)&As[k][trow * 8 + 4];
            float4 b  = *(const float4*)&Bs[(k0 + k) * DOUT + tcol * 4];
            unsigned long long bb0 = pack2(b.x, b.y);
            unsigned long long bb1 = pack2(b.z, b.w);
            float av[8] = {a0.x, a0.y, a0.z, a0.w, a1.x, a1.y, a1.z, a1.w};
#pragma unroll
            for (int i = 0; i < 8; ++i) {
                unsigned long long aa = pack2(av[i], av[i]);
                fma2(acc[i][0], aa, bb0);
                fma2(acc[i][1], aa, bb1);
            }
        }
        __syncthreads();
    }

#pragma unroll
    for (int i = 0; i < 8; ++i) {
        int row = block_row + trow * 8 + i;
        if (row < M) {
            float* cp = O + (size_t)row * DOUT + tcol * 4;
            float v0, v1, v2, v3;
            unpack2(acc[i][0], v0, v1);
            unpack2(acc[i][1], v2, v3);
            if (kk == 0) {
                float dd1 = d1[row], dd2 = d2[row];
                int c = tcol * 4;
                v0 += g_gc[c + 0] + dd1 * g_g1[c + 0] + dd2 * g_g2[c + 0];
                v1 += g_gc[c + 1] + dd1 * g_g1[c + 1] + dd2 * g_g2[c + 1];
                v2 += g_gc[c + 2] + dd1 * g_g1[c + 2] + dd2 * g_g2[c + 2];
                v3 += g_gc[c + 3] + dd1 * g_g1[c + 3] + dd2 * g_g2[c + 3];
            }
            cp[0] = v0; cp[1] = v1; cp[2] = v2; cp[3] = v3;
        }
    }
}

// ---------------- 64-wide edge scatter-add: dst += A . src (half-warp per edge) ----------------
__global__ void k_scatter64(const float* __restrict__ src, float* __restrict__ dst, int nE) {
    int gw   = (int)(((size_t)blockIdx.x * blockDim.x + threadIdx.x) >> 5);
    int lane = threadIdx.x & 31;
    int e    = 2 * gw + (lane >> 4);
    if (e >= nE) return;
    int l16 = lane & 15;
    int s = g_src[e];
    int d = g_dst[e];
    float4 v = *(const float4*)(src + (size_t)s * DOUT + l16 * 4);
    float* ap = dst + (size_t)d * DOUT + l16 * 4;
    asm volatile("red.global.add.v4.f32 [%0], {%1, %2, %3, %4};"
                 :: "l"(ap), "f"(v.x), "f"(v.y), "f"(v.z), "f"(v.w) : "memory");
}

// ---------------- host orchestration ----------------
extern "C" void kernel_launch(void* const* d_in, const int* in_sizes, int n_in,
                              void* d_out, int out_size)
{
    const float* x      = (const float*)d_in[0];
    const int*   ei32   = (const int*)d_in[1];
    const float* W_rel  = (const float*)d_in[2];
    const float* b_rel  = (const float*)d_in[3];
    const float* W_root = (const float*)d_in[4];
    const float* fc_w   = (const float*)d_in[5];
    const float* fc_b   = (const float*)d_in[6];
    float*       out    = (float*)d_out;

    int M  = in_sizes[0] / D;
    int nE = in_sizes[1] / 2;
    int L  = in_sizes[2] / (D * D);
    if (M > NN_MAX) M = NN_MAX;
    if (nE > NE_MAX) nE = NE_MAX;
    if (L > L_MAX) L = L_MAX;

    float *Ma, *Mb, *bA, *bB, *Vbase, *d1, *d2;
    cudaGetSymbolAddress((void**)&Ma, g_Ma);
    cudaGetSymbolAddress((void**)&Mb, g_Mb);
    cudaGetSymbolAddress((void**)&bA, g_bA);
    cudaGetSymbolAddress((void**)&bB, g_bB);
    cudaGetSymbolAddress((void**)&Vbase, g_V);
    cudaGetSymbolAddress((void**)&d1, g_d1);
    cudaGetSymbolAddress((void**)&d2, g_d2);

    // edges
    k_detect<<<1, 256>>>(ei32, in_sizes[1]);
    k_prep_edges<<<(nE + 255) / 256, 256>>>(ei32, nE, M);

    // weight recurrence (tiny)
    k_init_M<<<(KMAX * D * D + KMAX * D + 255) / 256, 256>>>();
    const float* Min = Ma;  float* Mout = Mb;
    const float* bin = bA;  float* bout = bB;
    for (int l = 1; l <= L; ++l) {
        const float* Wr = W_rel  + (size_t)(l - 1) * D * D;
        const float* Wt = W_root + (size_t)(l - 1) * D * D;
        const float* bl = b_rel  + (size_t)(l - 1) * D;
        k_stage<<<dim3(4, l + 1), 256>>>(Min, Mout, Wr, Wt, l);
        k_stage_beta<<<1, 128>>>(bin, bout, Wr, Wt, bl, l);
        const float* t1 = Min; Min = Mout; Mout = (float*)t1;
        const float* t2 = bin; bin = bout; bout = (float*)t2;
    }
    k_make_C<<<dim3(4, L + 1), 256>>>(Min, fc_w);
    k_make_gamma<<<1, 64>>>(bin, fc_w, fc_b, L);

    // degree vectors
    k_zero_d<<<(M + 255) / 256, 256>>>(M);
    k_deg1<<<(nE + 255) / 256, 256>>>(nE);
    k_deg2<<<(nE + 255) / 256, 256>>>(nE);

    // V_k = x0 @ C_k   (k=0 -> out with bias/degree epilogue)
    int gemm_blocks = (M + 127) / 128;
    k_gemm_proj<<<dim3(gemm_blocks, L + 1), 256>>>(x, d1, d2, out, M);

    // Horner: out = V0 + A(V1 + A(V2 + A V3))
    int scat_blocks = (nE + 15) / 16;    // 8 warps/block, 2 edges/warp
    for (int k = L; k >= 1; --k) {
        const float* s = Vbase + (size_t)(k - 1) * NN_MAX * DOUT;
        float*       t = (k == 1) ? out : (Vbase + (size_t)(k - 2) * NN_MAX * DOUT);
        k_scatter64<<<scat_blocks, 256>>>(s, t, nE);
    }
}

// round 6
// speedup vs baseline: 2.1720x; 2.0397x over previous
#include <cuda_runtime.h>
#include <cstdint>
#include <cstddef>

#define D        128
#define DOUT     64
#define NN_MAX   100000
#define NE_MAX   1600000
#define L_MAX    3
#define KMAX     (L_MAX + 1)

// ---------------- scratch (static device globals; no allocation) ----------------
__device__ __align__(256) float g_V [L_MAX][(size_t)NN_MAX * DOUT]; // Horner buffers V1..V3
__device__ __align__(256) float g_d1[NN_MAX];                       // indegree  (A·1)
__device__ __align__(256) float g_d2[NN_MAX];                       // A·indegree
__device__ __align__(256) float g_Ma[KMAX][D * D];                  // M recurrence dbl-buffer
__device__ __align__(256) float g_Mb[KMAX][D * D];
__device__ __align__(256) float g_bA[KMAX][D];                      // beta dbl-buffer
__device__ __align__(256) float g_bB[KMAX][D];
__device__ __align__(256) float g_C [KMAX][D * DOUT];               // C_k[p][n], p-major
__device__ __align__(256) float g_gc[DOUT];                         // gamma0 + fc_b
__device__ __align__(256) float g_g1[DOUT];
__device__ __align__(256) float g_g2[DOUT];
__device__ __align__(256) int   g_src[NE_MAX];
__device__ __align__(256) int   g_dst[NE_MAX];
__device__ int g_is64;

// ---------------- f32x2 packed-FMA helpers (Blackwell FFMA2) ----------------
__device__ __forceinline__ unsigned long long pack2(float lo, float hi) {
    unsigned long long r;
    asm("mov.b64 %0, {%1, %2};" : "=l"(r) : "f"(lo), "f"(hi));
    return r;
}
__device__ __forceinline__ void unpack2(unsigned long long v, float& lo, float& hi) {
    asm("mov.b64 {%0, %1}, %2;" : "=f"(lo), "=f"(hi) : "l"(v));
}
__device__ __forceinline__ void fma2(unsigned long long& acc, unsigned long long a,
                                     unsigned long long b) {
    asm("fma.rn.f32x2 %0, %1, %2, %0;" : "+l"(acc) : "l"(a), "l"(b));
}

// ---------------- edge-index width detection (int64 vs int32) ----------------
__global__ void k_detect(const int* __restrict__ ei32, int n32) {
    __shared__ int any;
    if (threadIdx.x == 0) any = 0;
    __syncthreads();
    for (int i = threadIdx.x; i < 2048; i += blockDim.x) {
        int idx = 2 * i + 1;
        if (idx < n32 && ei32[idx] != 0) any = 1;
    }
    __syncthreads();
    if (threadIdx.x == 0) g_is64 = (any == 0) ? 1 : 0;
}

__global__ void k_prep_edges(const int* __restrict__ ei32, int nE, int M) {
    int i = blockIdx.x * blockDim.x + threadIdx.x;
    if (i >= nE) return;
    int s, d;
    if (g_is64) {
        const long long* e = (const long long*)ei32;
        s = (int)e[i];
        d = (int)e[i + (size_t)nE];
    } else {
        s = ei32[i];
        d = ei32[i + (size_t)nE];
    }
    if (s < 0) s = 0; if (s >= M) s = M - 1;
    if (d < 0) d = 0; if (d >= M) d = M - 1;
    g_src[i] = s;
    g_dst[i] = d;
}

// ---------------- tiny weight-recurrence precompute ----------------
// M_{0,0} = I; beta_0 = 0
__global__ void k_init_M() {
    int i = blockIdx.x * blockDim.x + threadIdx.x;
    int tot = KMAX * D * D;
    if (i < tot) {
        int k = i / (D * D);
        int r = i % (D * D);
        ((float*)g_Ma)[i] = (k == 0 && (r / D) == (r % D)) ? 1.f : 0.f;
    } else if (i < tot + KMAX * D) {
        ((float*)g_bA)[i - tot] = 0.f;
    }
}

// Stage l (1-based): Mout_k = Min_k @ Wt^T + Min_{k-1} @ Wr^T.
// grid (8 = 4 p-tiles x 2 n-halves, l+1), 256 threads.
// smem-tiled: lane = p-row (padded A tiles, conflict-free LDS.128),
// warp = n-group (W tile reads are uniform broadcast).
__global__ __launch_bounds__(256) void k_stage(
    const float* __restrict__ Min, float* __restrict__ Mout,
    const float* __restrict__ Wr, const float* __restrict__ Wt, int l)
{
    __shared__ float sT[32][132];
    __shared__ float sR[32][132];
    __shared__ float sWt[64][16];
    __shared__ float sWr[64][16];

    const int k   = blockIdx.y;
    const int p0  = (blockIdx.x >> 1) * 32;
    const int nh  = (blockIdx.x & 1) * 64;
    const int tid = threadIdx.x;

    const bool vT = (k <= l - 1);
    const bool vR = (k >= 1);
    for (int i = tid * 4; i < 32 * 128; i += 1024) {
        int p = i >> 7, q = i & 127;
        float4 t = vT ? *(const float4*)&Min[(size_t)k * D * D + (p0 + p) * D + q]
                      : make_float4(0.f, 0.f, 0.f, 0.f);
        float4 r = vR ? *(const float4*)&Min[(size_t)(k - 1) * D * D + (p0 + p) * D + q]
                      : make_float4(0.f, 0.f, 0.f, 0.f);
        *(float4*)&sT[p][q] = t;
        *(float4*)&sR[p][q] = r;
    }

    const int p  = tid & 31;
    const int nl = (tid >> 5) * 8;       // 8 warps x 8 n (local)
    float acc[8] = {0.f, 0.f, 0.f, 0.f, 0.f, 0.f, 0.f, 0.f};

#pragma unroll 1
    for (int qt = 0; qt < 8; ++qt) {
        int q0 = qt * 16;
        __syncthreads();
        {   // load W tiles [64 local-n][16 q], coalesced; 256 float4 = 1 per thread
            int i = tid * 4;
            int n = i >> 4, qq = i & 15;
            *(float4*)&sWt[n][qq] = *(const float4*)&Wt[(size_t)(nh + n) * D + q0 + qq];
            *(float4*)&sWr[n][qq] = *(const float4*)&Wr[(size_t)(nh + n) * D + q0 + qq];
        }
        __syncthreads();
#pragma unroll
        for (int q4 = 0; q4 < 4; ++q4) {
            float4 t = *(const float4*)&sT[p][q0 + q4 * 4];
            float4 r = *(const float4*)&sR[p][q0 + q4 * 4];
#pragma unroll
            for (int n = 0; n < 8; ++n) {
                float4 wt = *(const float4*)&sWt[nl + n][q4 * 4];
                float4 wr = *(const float4*)&sWr[nl + n][q4 * 4];
                acc[n] += t.x * wt.x + t.y * wt.y + t.z * wt.z + t.w * wt.w
                        + r.x * wr.x + r.y * wr.y + r.z * wr.z + r.w * wr.w;
            }
        }
    }

#pragma unroll
    for (int n = 0; n < 8; ++n)
        Mout[(size_t)k * D * D + (p0 + p) * D + (nh + nl + n)] = acc[n];
}

// beta_out_k = Wt @ beta_in_k + Wr @ beta_in_{k-1} (+ b_l if k==0); inputs valid [0, l-2].
__global__ void k_stage_beta(const float* __restrict__ bin, float* __restrict__ bout,
                             const float* __restrict__ Wr, const float* __restrict__ Wt,
                             const float* __restrict__ bl, int l) {
    __shared__ float sb[L_MAX + 1][D];   // row L_MAX stays zero
    int n = threadIdx.x;                 // 128 threads
#pragma unroll
    for (int k = 0; k < L_MAX; ++k)
        sb[k][n] = (k <= l - 2) ? bin[k * D + n] : 0.f;
    sb[L_MAX][n] = 0.f;
    __syncthreads();

    for (int k = 0; k < l; ++k) {
        const float* tp = sb[k];                          // zero when k > l-2
        const float* rp = (k >= 1) ? sb[k - 1] : sb[L_MAX];
        float acc = (k == 0) ? bl[n] : 0.f;
#pragma unroll 4
        for (int q4 = 0; q4 < 32; ++q4) {
            float4 wt = *(const float4*)&Wt[(size_t)n * D + q4 * 4];
            float4 wr = *(const float4*)&Wr[(size_t)n * D + q4 * 4];
            acc += wt.x * tp[q4 * 4 + 0] + wt.y * tp[q4 * 4 + 1]
                 + wt.z * tp[q4 * 4 + 2] + wt.w * tp[q4 * 4 + 3]
                 + wr.x * rp[q4 * 4 + 0] + wr.y * rp[q4 * 4 + 1]
                 + wr.z * rp[q4 * 4 + 2] + wr.w * rp[q4 * 4 + 3];
        }
        bout[k * D + n] = acc;
    }
}

// C_k[p][n] = sum_q M3_k[p][q] * fc_w[n][q]     grid (4, L+1), 256 threads
__global__ __launch_bounds__(256) void k_make_C(const float* __restrict__ M3,
                                                const float* __restrict__ fcw) {
    __shared__ float sM[32][132];
    __shared__ float sW[64][16];
    const int k   = blockIdx.y;
    const int p0  = blockIdx.x * 32;
    const int tid = threadIdx.x;

    for (int i = tid * 4; i < 32 * 128; i += 1024) {
        int p = i >> 7, q = i & 127;
        *(float4*)&sM[p][q] = *(const float4*)&M3[(size_t)k * D * D + (p0 + p) * D + q];
    }

    const int p  = tid & 31;
    const int nl = (tid >> 5) * 8;       // 8 warps x 8 n = 64
    float acc[8] = {0.f, 0.f, 0.f, 0.f, 0.f, 0.f, 0.f, 0.f};

#pragma unroll 1
    for (int qt = 0; qt < 8; ++qt) {
        int q0 = qt * 16;
        __syncthreads();
        {
            int i = tid * 4;
            int n = i >> 4, qq = i & 15;
            *(float4*)&sW[n][qq] = *(const float4*)&fcw[(size_t)n * D + q0 + qq];
        }
        __syncthreads();
#pragma unroll
        for (int q4 = 0; q4 < 4; ++q4) {
            float4 m = *(const float4*)&sM[p][q0 + q4 * 4];
#pragma unroll
            for (int n = 0; n < 8; ++n) {
                float4 w = *(const float4*)&sW[nl + n][q4 * 4];
                acc[n] += m.x * w.x + m.y * w.y + m.z * w.z + m.w * w.w;
            }
        }
    }
#pragma unroll
    for (int n = 0; n < 8; ++n)
        g_C[k][(p0 + p) * DOUT + nl + n] = acc[n];
}

__global__ void k_make_gamma(const float* __restrict__ b3, const float* __restrict__ fcw,
                             const float* __restrict__ fcb, int L) {
    int n = threadIdx.x;   // 0..63
    float a0 = fcb[n], a1 = 0.f, a2 = 0.f;
#pragma unroll 4
    for (int q4 = 0; q4 < 32; ++q4) {
        float4 w = *(const float4*)&fcw[(size_t)n * D + q4 * 4];
        float4 v0 = *(const float4*)&b3[0 * D + q4 * 4];
        a0 += w.x * v0.x + w.y * v0.y + w.z * v0.z + w.w * v0.w;
        if (L >= 2) {
            float4 v1 = *(const float4*)&b3[1 * D + q4 * 4];
            a1 += w.x * v1.x + w.y * v1.y + w.z * v1.z + w.w * v1.w;
        }
        if (L >= 3) {
            float4 v2 = *(const float4*)&b3[2 * D + q4 * 4];
            a2 += w.x * v2.x + w.y * v2.y + w.z * v2.z + w.w * v2.w;
        }
    }
    g_gc[n] = a0; g_g1[n] = a1; g_g2[n] = a2;
}

// ---------------- degree vectors ----------------
__global__ void k_zero_d(int M) {
    int i = blockIdx.x * blockDim.x + threadIdx.x;
    if (i < M) { g_d1[i] = 0.f; g_d2[i] = 0.f; }
}
__global__ void k_deg1(int nE) {
    int i = blockIdx.x * blockDim.x + threadIdx.x;
    if (i < nE) {
        float* p = &g_d1[g_dst[i]];
        asm volatile("red.global.add.f32 [%0], %1;" :: "l"(p), "f"(1.0f) : "memory");
    }
}
__global__ void k_deg2(int nE) {
    int i = blockIdx.x * blockDim.x + threadIdx.x;
    if (i < nE) {
        float v = g_d1[g_src[i]];
        float* p = &g_d2[g_dst[i]];
        asm volatile("red.global.add.f32 [%0], %1;" :: "l"(p), "f"(v) : "memory");
    }
}

// ---------------- projection GEMM: V_k = x0 @ C_k (+ bias terms for k==0) ----------------
// BM=128, BN=64, full-K B in smem, 256 threads, thread tile 8x4. grid (tiles, L+1).
__global__ __launch_bounds__(256, 2) void k_gemm_proj(
    const float* __restrict__ A, const float* __restrict__ d1,
    const float* __restrict__ d2, float* __restrict__ out, int M)
{
    __shared__ float Bs[D * DOUT];   // 32 KB
    __shared__ float As[8][128];

    const int kk = blockIdx.y;
    float* O = (kk == 0) ? out : &g_V[kk - 1][0];
    const float* B = &g_C[kk][0];

    const int tid  = threadIdx.x;
    const int trow = tid >> 4;
    const int tcol = tid & 15;
    const int block_row = blockIdx.x * 128;

#pragma unroll
    for (int v = 0; v < 8; ++v) {
        int o = v * 1024 + tid * 4;
        *(float4*)&Bs[o] = *(const float4*)&B[o];
    }

    const int arow = tid >> 1;
    const int akk  = (tid & 1) << 2;
    int grow = block_row + arow;
    if (grow >= M) grow = M - 1;

    unsigned long long acc[8][2];
#pragma unroll
    for (int i = 0; i < 8; i++) { acc[i][0] = 0ull; acc[i][1] = 0ull; }

    float4 aref = *(const float4*)(A + (size_t)grow * D + akk);
    __syncthreads();

#pragma unroll 1
    for (int s = 0; s < 16; ++s) {
        As[akk + 0][arow] = aref.x;
        As[akk + 1][arow] = aref.y;
        As[akk + 2][arow] = aref.z;
        As[akk + 3][arow] = aref.w;
        __syncthreads();

        if (s + 1 < 16) {
            int kb = (s + 1) * 8;
            aref = *(const float4*)(A + (size_t)grow * D + kb + akk);
        }

        int k0 = s * 8;
#pragma unroll
        for (int k = 0; k < 8; ++k) {
            float4 a0 = *(const float4*)&As[k][trow * 8];
            float4 a1 = *(const float4*)&As[k][trow * 8 + 4];
            float4 b  = *(const float4*)&Bs[(k0 + k) * DOUT + tcol * 4];
            unsigned long long bb0 = pack2(b.x, b.y);
            unsigned long long bb1 = pack2(b.z, b.w);
            float av[8] = {a0.x, a0.y, a0.z, a0.w, a1.x, a1.y, a1.z, a1.w};
#pragma unroll
            for (int i = 0; i < 8; ++i) {
                unsigned long long aa = pack2(av[i], av[i]);
                fma2(acc[i][0], aa, bb0);
                fma2(acc[i][1], aa, bb1);
            }
        }
        __syncthreads();
    }

#pragma unroll
    for (int i = 0; i < 8; ++i) {
        int row = block_row + trow * 8 + i;
        if (row < M) {
            float* cp = O + (size_t)row * DOUT + tcol * 4;
            float v0, v1, v2, v3;
            unpack2(acc[i][0], v0, v1);
            unpack2(acc[i][1], v2, v3);
            if (kk == 0) {
                float dd1 = d1[row], dd2 = d2[row];
                int c = tcol * 4;
                v0 += g_gc[c + 0] + dd1 * g_g1[c + 0] + dd2 * g_g2[c + 0];
                v1 += g_gc[c + 1] + dd1 * g_g1[c + 1] + dd2 * g_g2[c + 1];
                v2 += g_gc[c + 2] + dd1 * g_g1[c + 2] + dd2 * g_g2[c + 2];
                v3 += g_gc[c + 3] + dd1 * g_g1[c + 3] + dd2 * g_g2[c + 3];
            }
            cp[0] = v0; cp[1] = v1; cp[2] = v2; cp[3] = v3;
        }
    }
}

// ---------------- 64-wide edge scatter-add: dst += A . src (half-warp per edge) ----------------
__global__ void k_scatter64(const float* __restrict__ src, float* __restrict__ dst, int nE) {
    int gw   = (int)(((size_t)blockIdx.x * blockDim.x + threadIdx.x) >> 5);
    int lane = threadIdx.x & 31;
    int e    = 2 * gw + (lane >> 4);
    if (e >= nE) return;
    int l16 = lane & 15;
    int s = g_src[e];
    int d = g_dst[e];
    float4 v = *(const float4*)(src + (size_t)s * DOUT + l16 * 4);
    float* ap = dst + (size_t)d * DOUT + l16 * 4;
    asm volatile("red.global.add.v4.f32 [%0], {%1, %2, %3, %4};"
                 :: "l"(ap), "f"(v.x), "f"(v.y), "f"(v.z), "f"(v.w) : "memory");
}

// ---------------- host orchestration ----------------
extern "C" void kernel_launch(void* const* d_in, const int* in_sizes, int n_in,
                              void* d_out, int out_size)
{
    const float* x      = (const float*)d_in[0];
    const int*   ei32   = (const int*)d_in[1];
    const float* W_rel  = (const float*)d_in[2];
    const float* b_rel  = (const float*)d_in[3];
    const float* W_root = (const float*)d_in[4];
    const float* fc_w   = (const float*)d_in[5];
    const float* fc_b   = (const float*)d_in[6];
    float*       out    = (float*)d_out;

    int M  = in_sizes[0] / D;
    int nE = in_sizes[1] / 2;
    int L  = in_sizes[2] / (D * D);
    if (M > NN_MAX) M = NN_MAX;
    if (nE > NE_MAX) nE = NE_MAX;
    if (L > L_MAX) L = L_MAX;

    float *Ma, *Mb, *bA, *bB, *Vbase, *d1, *d2;
    cudaGetSymbolAddress((void**)&Ma, g_Ma);
    cudaGetSymbolAddress((void**)&Mb, g_Mb);
    cudaGetSymbolAddress((void**)&bA, g_bA);
    cudaGetSymbolAddress((void**)&bB, g_bB);
    cudaGetSymbolAddress((void**)&Vbase, g_V);
    cudaGetSymbolAddress((void**)&d1, g_d1);
    cudaGetSymbolAddress((void**)&d2, g_d2);

    // edges
    k_detect<<<1, 256>>>(ei32, in_sizes[1]);
    k_prep_edges<<<(nE + 255) / 256, 256>>>(ei32, nE, M);

    // weight recurrence (now smem-tiled; ~5us per stage)
    k_init_M<<<(KMAX * D * D + KMAX * D + 255) / 256, 256>>>();
    const float* Min = Ma;  float* Mout = Mb;
    const float* bin = bA;  float* bout = bB;
    for (int l = 1; l <= L; ++l) {
        const float* Wr = W_rel  + (size_t)(l - 1) * D * D;
        const float* Wt = W_root + (size_t)(l - 1) * D * D;
        const float* bl = b_rel  + (size_t)(l - 1) * D;
        k_stage<<<dim3(8, l + 1), 256>>>(Min, Mout, Wr, Wt, l);
        k_stage_beta<<<1, 128>>>(bin, bout, Wr, Wt, bl, l);
        const float* t1 = Min; Min = Mout; Mout = (float*)t1;
        const float* t2 = bin; bin = bout; bout = (float*)t2;
    }
    k_make_C<<<dim3(4, L + 1), 256>>>(Min, fc_w);
    k_make_gamma<<<1, 64>>>(bin, fc_w, fc_b, L);

    // degree vectors
    k_zero_d<<<(M + 255) / 256, 256>>>(M);
    k_deg1<<<(nE + 255) / 256, 256>>>(nE);
    k_deg2<<<(nE + 255) / 256, 256>>>(nE);

    // V_k = x0 @ C_k   (k=0 -> out with bias/degree epilogue)
    int gemm_blocks = (M + 127) / 128;
    k_gemm_proj<<<dim3(gemm_blocks, L + 1), 256>>>(x, d1, d2, out, M);

    // Horner: out = V0 + A(V1 + A(V2 + A V3))
    int scat_blocks = (nE + 15) / 16;    // 8 warps/block, 2 edges/warp
    for (int k = L; k >= 1; --k) {
        const float* s = Vbase + (size_t)(k - 1) * NN_MAX * DOUT;
        float*       t = (k == 1) ? out : (Vbase + (size_t)(k - 2) * NN_MAX * DOUT);
        k_scatter64<<<scat_blocks, 256>>>(s, t, nE);
    }
}

// round 7
// speedup vs baseline: 3.0239x; 1.3922x over previous
#include <cuda_runtime.h>
#include <cstdint>
#include <cstddef>

#define D        128
#define DOUT     64
#define NN_MAX   100000
#define NE_MAX   1600000
#define L_MAX    3
#define KMAX     (L_MAX + 1)
#define SCAN_BLK 1024
#define NB_MAX   ((NN_MAX + SCAN_BLK - 1) / SCAN_BLK)   // 98 <= 128

// ---------------- scratch (static device globals; no allocation) ----------------
__device__ __align__(256) float g_V [L_MAX][(size_t)NN_MAX * DOUT]; // Horner buffers V1..V3
__device__ __align__(256) float g_d1[NN_MAX];                       // indegree  (A·1)
__device__ __align__(256) float g_d2[NN_MAX];                       // A·indegree
__device__ __align__(256) float g_Ma[KMAX][D * D];                  // M recurrence dbl-buffer
__device__ __align__(256) float g_Mb[KMAX][D * D];
__device__ __align__(256) float g_bA[KMAX][D];                      // beta dbl-buffer
__device__ __align__(256) float g_bB[KMAX][D];
__device__ __align__(256) float g_C [KMAX][D * DOUT];               // C_k[p][n], p-major
__device__ __align__(256) float g_gc[DOUT];                         // gamma0 + fc_b
__device__ __align__(256) float g_g1[DOUT];
__device__ __align__(256) float g_g2[DOUT];
__device__ __align__(256) int   g_src [NE_MAX];
__device__ __align__(256) int   g_dst [NE_MAX];
__device__ __align__(256) int   g_csr [NE_MAX];       // src ids sorted by dst
__device__ __align__(256) int   g_ptr [NN_MAX + 1];   // CSR row pointers
__device__ __align__(256) int   g_cur [NN_MAX];       // fill cursors
__device__ __align__(256) int   g_cnt [NN_MAX];       // dst histogram
__device__ __align__(256) int   g_bsum[NB_MAX];
__device__ int g_is64;

// ---------------- f32x2 packed-FMA helpers (Blackwell FFMA2) ----------------
__device__ __forceinline__ unsigned long long pack2(float lo, float hi) {
    unsigned long long r;
    asm("mov.b64 %0, {%1, %2};" : "=l"(r) : "f"(lo), "f"(hi));
    return r;
}
__device__ __forceinline__ void unpack2(unsigned long long v, float& lo, float& hi) {
    asm("mov.b64 {%0, %1}, %2;" : "=f"(lo), "=f"(hi) : "l"(v));
}
__device__ __forceinline__ void fma2(unsigned long long& acc, unsigned long long a,
                                     unsigned long long b) {
    asm("fma.rn.f32x2 %0, %1, %2, %0;" : "+l"(acc) : "l"(a), "l"(b));
}

// ---------------- edge-index width detection (int64 vs int32) ----------------
__global__ void k_detect(const int* __restrict__ ei32, int n32) {
    __shared__ int any;
    if (threadIdx.x == 0) any = 0;
    __syncthreads();
    for (int i = threadIdx.x; i < 2048; i += blockDim.x) {
        int idx = 2 * i + 1;
        if (idx < n32 && ei32[idx] != 0) any = 1;
    }
    __syncthreads();
    if (threadIdx.x == 0) g_is64 = (any == 0) ? 1 : 0;
}

__global__ void k_zero_cnt(int M) {
    int i = blockIdx.x * blockDim.x + threadIdx.x;
    if (i < M) g_cnt[i] = 0;
}

// decode edges + fused dst histogram
__global__ void k_prep_edges(const int* __restrict__ ei32, int nE, int M) {
    int i = blockIdx.x * blockDim.x + threadIdx.x;
    if (i >= nE) return;
    int s, d;
    if (g_is64) {
        const long long* e = (const long long*)ei32;
        s = (int)e[i];
        d = (int)e[i + (size_t)nE];
    } else {
        s = ei32[i];
        d = ei32[i + (size_t)nE];
    }
    if (s < 0) s = 0; if (s >= M) s = M - 1;
    if (d < 0) d = 0; if (d >= M) d = M - 1;
    g_src[i] = s;
    g_dst[i] = d;
    atomicAdd(&g_cnt[d], 1);
}

// ---------------- CSR build: two-level exclusive scan + cursor fill ----------------
__global__ void k_scan1(int M) {
    __shared__ int sh[SCAN_BLK];
    int base = blockIdx.x * SCAN_BLK;
    int i = base + threadIdx.x;
    int v = (i < M) ? g_cnt[i] : 0;
    sh[threadIdx.x] = v;
    __syncthreads();
#pragma unroll
    for (int off = 1; off < SCAN_BLK; off <<= 1) {
        int t = (threadIdx.x >= off) ? sh[threadIdx.x - off] : 0;
        __syncthreads();
        sh[threadIdx.x] += t;
        __syncthreads();
    }
    if (i < M) g_ptr[i] = sh[threadIdx.x] - v;       // exclusive
    if (threadIdx.x == SCAN_BLK - 1) g_bsum[blockIdx.x] = sh[threadIdx.x];
}

__global__ void k_scan2(int nB) {
    __shared__ int sh[128];
    int v = (threadIdx.x < nB) ? g_bsum[threadIdx.x] : 0;
    sh[threadIdx.x] = v;
    __syncthreads();
#pragma unroll
    for (int off = 1; off < 128; off <<= 1) {
        int t = (threadIdx.x >= off) ? sh[threadIdx.x - off] : 0;
        __syncthreads();
        sh[threadIdx.x] += t;
        __syncthreads();
    }
    if (threadIdx.x < nB) g_bsum[threadIdx.x] = sh[threadIdx.x] - v;   // exclusive
}

// finalize rowptr, init cursors, emit d1 = float(count)
__global__ void k_scan3(int M, int nE) {
    int i = blockIdx.x * blockDim.x + threadIdx.x;
    if (i < M) {
        int p = g_ptr[i] + g_bsum[i / SCAN_BLK];
        g_ptr[i] = p;
        g_cur[i] = p;
        g_d1[i] = (float)g_cnt[i];
    }
    if (i == 0) g_ptr[M] = nE;
}

__global__ void k_fill(int nE) {
    int i = blockIdx.x * blockDim.x + threadIdx.x;
    if (i >= nE) return;
    int d = g_dst[i];
    int slot = atomicAdd(&g_cur[d], 1);
    g_csr[slot] = g_src[i];
}

// d2[i] = sum_{j in N(i)} d1[j]   (thread per node via CSR)
__global__ void k_d2(int M) {
    int i = blockIdx.x * blockDim.x + threadIdx.x;
    if (i >= M) return;
    int beg = g_ptr[i], end = g_ptr[i + 1];
    float s = 0.f;
    for (int e = beg; e < end; ++e) s += g_d1[g_csr[e]];
    g_d2[i] = s;
}

// ---------------- tiny weight-recurrence precompute ----------------
__global__ void k_init_M() {
    int i = blockIdx.x * blockDim.x + threadIdx.x;
    int tot = KMAX * D * D;
    if (i < tot) {
        int k = i / (D * D);
        int r = i % (D * D);
        ((float*)g_Ma)[i] = (k == 0 && (r / D) == (r % D)) ? 1.f : 0.f;
    } else if (i < tot + KMAX * D) {
        ((float*)g_bA)[i - tot] = 0.f;
    }
}

// Stage l (1-based): Mout_k = Min_k @ Wt^T + Min_{k-1} @ Wr^T.
__global__ __launch_bounds__(256) void k_stage(
    const float* __restrict__ Min, float* __restrict__ Mout,
    const float* __restrict__ Wr, const float* __restrict__ Wt, int l)
{
    __shared__ float sT[32][132];
    __shared__ float sR[32][132];
    __shared__ float sWt[64][16];
    __shared__ float sWr[64][16];

    const int k   = blockIdx.y;
    const int p0  = (blockIdx.x >> 1) * 32;
    const int nh  = (blockIdx.x & 1) * 64;
    const int tid = threadIdx.x;

    const bool vT = (k <= l - 1);
    const bool vR = (k >= 1);
    for (int i = tid * 4; i < 32 * 128; i += 1024) {
        int p = i >> 7, q = i & 127;
        float4 t = vT ? *(const float4*)&Min[(size_t)k * D * D + (p0 + p) * D + q]
                      : make_float4(0.f, 0.f, 0.f, 0.f);
        float4 r = vR ? *(const float4*)&Min[(size_t)(k - 1) * D * D + (p0 + p) * D + q]
                      : make_float4(0.f, 0.f, 0.f, 0.f);
        *(float4*)&sT[p][q] = t;
        *(float4*)&sR[p][q] = r;
    }

    const int p  = tid & 31;
    const int nl = (tid >> 5) * 8;
    float acc[8] = {0.f, 0.f, 0.f, 0.f, 0.f, 0.f, 0.f, 0.f};

#pragma unroll 1
    for (int qt = 0; qt < 8; ++qt) {
        int q0 = qt * 16;
        __syncthreads();
        {
            int i = tid * 4;
            int n = i >> 4, qq = i & 15;
            *(float4*)&sWt[n][qq] = *(const float4*)&Wt[(size_t)(nh + n) * D + q0 + qq];
            *(float4*)&sWr[n][qq] = *(const float4*)&Wr[(size_t)(nh + n) * D + q0 + qq];
        }
        __syncthreads();
#pragma unroll
        for (int q4 = 0; q4 < 4; ++q4) {
            float4 t = *(const float4*)&sT[p][q0 + q4 * 4];
            float4 r = *(const float4*)&sR[p][q0 + q4 * 4];
#pragma unroll
            for (int n = 0; n < 8; ++n) {
                float4 wt = *(const float4*)&sWt[nl + n][q4 * 4];
                float4 wr = *(const float4*)&sWr[nl + n][q4 * 4];
                acc[n] += t.x * wt.x + t.y * wt.y + t.z * wt.z + t.w * wt.w
                        + r.x * wr.x + r.y * wr.y + r.z * wr.z + r.w * wr.w;
            }
        }
    }

#pragma unroll
    for (int n = 0; n < 8; ++n)
        Mout[(size_t)k * D * D + (p0 + p) * D + (nh + nl + n)] = acc[n];
}

__global__ void k_stage_beta(const float* __restrict__ bin, float* __restrict__ bout,
                             const float* __restrict__ Wr, const float* __restrict__ Wt,
                             const float* __restrict__ bl, int l) {
    __shared__ float sb[L_MAX + 1][D];
    int n = threadIdx.x;
#pragma unroll
    for (int k = 0; k < L_MAX; ++k)
        sb[k][n] = (k <= l - 2) ? bin[k * D + n] : 0.f;
    sb[L_MAX][n] = 0.f;
    __syncthreads();

    for (int k = 0; k < l; ++k) {
        const float* tp = sb[k];
        const float* rp = (k >= 1) ? sb[k - 1] : sb[L_MAX];
        float acc = (k == 0) ? bl[n] : 0.f;
#pragma unroll 4
        for (int q4 = 0; q4 < 32; ++q4) {
            float4 wt = *(const float4*)&Wt[(size_t)n * D + q4 * 4];
            float4 wr = *(const float4*)&Wr[(size_t)n * D + q4 * 4];
            acc += wt.x * tp[q4 * 4 + 0] + wt.y * tp[q4 * 4 + 1]
                 + wt.z * tp[q4 * 4 + 2] + wt.w * tp[q4 * 4 + 3]
                 + wr.x * rp[q4 * 4 + 0] + wr.y * rp[q4 * 4 + 1]
                 + wr.z * rp[q4 * 4 + 2] + wr.w * rp[q4 * 4 + 3];
        }
        bout[k * D + n] = acc;
    }
}

__global__ __launch_bounds__(256) void k_make_C(const float* __restrict__ M3,
                                                const float* __restrict__ fcw) {
    __shared__ float sM[32][132];
    __shared__ float sW[64][16];
    const int k   = blockIdx.y;
    const int p0  = blockIdx.x * 32;
    const int tid = threadIdx.x;

    for (int i = tid * 4; i < 32 * 128; i += 1024) {
        int p = i >> 7, q = i & 127;
        *(float4*)&sM[p][q] = *(const float4*)&M3[(size_t)k * D * D + (p0 + p) * D + q];
    }

    const int p  = tid & 31;
    const int nl = (tid >> 5) * 8;
    float acc[8] = {0.f, 0.f, 0.f, 0.f, 0.f, 0.f, 0.f, 0.f};

#pragma unroll 1
    for (int qt = 0; qt < 8; ++qt) {
        int q0 = qt * 16;
        __syncthreads();
        {
            int i = tid * 4;
            int n = i >> 4, qq = i & 15;
            *(float4*)&sW[n][qq] = *(const float4*)&fcw[(size_t)n * D + q0 + qq];
        }
        __syncthreads();
#pragma unroll
        for (int q4 = 0; q4 < 4; ++q4) {
            float4 m = *(const float4*)&sM[p][q0 + q4 * 4];
#pragma unroll
            for (int n = 0; n < 8; ++n) {
                float4 w = *(const float4*)&sW[nl + n][q4 * 4];
                acc[n] += m.x * w.x + m.y * w.y + m.z * w.z + m.w * w.w;
            }
        }
    }
#pragma unroll
    for (int n = 0; n < 8; ++n)
        g_C[k][(p0 + p) * DOUT + nl + n] = acc[n];
}

__global__ void k_make_gamma(const float* __restrict__ b3, const float* __restrict__ fcw,
                             const float* __restrict__ fcb, int L) {
    int n = threadIdx.x;
    float a0 = fcb[n], a1 = 0.f, a2 = 0.f;
#pragma unroll 4
    for (int q4 = 0; q4 < 32; ++q4) {
        float4 w = *(const float4*)&fcw[(size_t)n * D + q4 * 4];
        float4 v0 = *(const float4*)&b3[0 * D + q4 * 4];
        a0 += w.x * v0.x + w.y * v0.y + w.z * v0.z + w.w * v0.w;
        if (L >= 2) {
            float4 v1 = *(const float4*)&b3[1 * D + q4 * 4];
            a1 += w.x * v1.x + w.y * v1.y + w.z * v1.z + w.w * v1.w;
        }
        if (L >= 3) {
            float4 v2 = *(const float4*)&b3[2 * D + q4 * 4];
            a2 += w.x * v2.x + w.y * v2.y + w.z * v2.z + w.w * v2.w;
        }
    }
    g_gc[n] = a0; g_g1[n] = a1; g_g2[n] = a2;
}

// ---------------- projection GEMM: V_k = x0 @ C_k (+ bias terms for k==0) ----------------
__global__ __launch_bounds__(256, 2) void k_gemm_proj(
    const float* __restrict__ A, const float* __restrict__ d1,
    const float* __restrict__ d2, float* __restrict__ out, int M)
{
    __shared__ float Bs[D * DOUT];
    __shared__ float As[8][128];

    const int kk = blockIdx.y;
    float* O = (kk == 0) ? out : &g_V[kk - 1][0];
    const float* B = &g_C[kk][0];

    const int tid  = threadIdx.x;
    const int trow = tid >> 4;
    const int tcol = tid & 15;
    const int block_row = blockIdx.x * 128;

#pragma unroll
    for (int v = 0; v < 8; ++v) {
        int o = v * 1024 + tid * 4;
        *(float4*)&Bs[o] = *(const float4*)&B[o];
    }

    const int arow = tid >> 1;
    const int akk  = (tid & 1) << 2;
    int grow = block_row + arow;
    if (grow >= M) grow = M - 1;

    unsigned long long acc[8][2];
#pragma unroll
    for (int i = 0; i < 8; i++) { acc[i][0] = 0ull; acc[i][1] = 0ull; }

    float4 aref = *(const float4*)(A + (size_t)grow * D + akk);
    __syncthreads();

#pragma unroll 1
    for (int s = 0; s < 16; ++s) {
        As[akk + 0][arow] = aref.x;
        As[akk + 1][arow] = aref.y;
        As[akk + 2][arow] = aref.z;
        As[akk + 3][arow] = aref.w;
        __syncthreads();

        if (s + 1 < 16) {
            int kb = (s + 1) * 8;
            aref = *(const float4*)(A + (size_t)grow * D + kb + akk);
        }

        int k0 = s * 8;
#pragma unroll
        for (int k = 0; k < 8; ++k) {
            float4 a0 = *(const float4*)&As[k][trow * 8];
            float4 a1 = *(const float4*)&As[k][trow * 8 + 4];
            float4 b  = *(const float4*)&Bs[(k0 + k) * DOUT + tcol * 4];
            unsigned long long bb0 = pack2(b.x, b.y);
            unsigned long long bb1 = pack2(b.z, b.w);
            float av[8] = {a0.x, a0.y, a0.z, a0.w, a1.x, a1.y, a1.z, a1.w};
#pragma unroll
            for (int i = 0; i < 8; ++i) {
                unsigned long long aa = pack2(av[i], av[i]);
                fma2(acc[i][0], aa, bb0);
                fma2(acc[i][1], aa, bb1);
            }
        }
        __syncthreads();
    }

#pragma unroll
    for (int i = 0; i < 8; ++i) {
        int row = block_row + trow * 8 + i;
        if (row < M) {
            float* cp = O + (size_t)row * DOUT + tcol * 4;
            float v0, v1, v2, v3;
            unpack2(acc[i][0], v0, v1);
            unpack2(acc[i][1], v2, v3);
            if (kk == 0) {
                float dd1 = d1[row], dd2 = d2[row];
                int c = tcol * 4;
                v0 += g_gc[c + 0] + dd1 * g_g1[c + 0] + dd2 * g_g2[c + 0];
                v1 += g_gc[c + 1] + dd1 * g_g1[c + 1] + dd2 * g_g2[c + 1];
                v2 += g_gc[c + 2] + dd1 * g_g1[c + 2] + dd2 * g_g2[c + 2];
                v3 += g_gc[c + 3] + dd1 * g_g1[c + 3] + dd2 * g_g2[c + 3];
            }
            cp[0] = v0; cp[1] = v1; cp[2] = v2; cp[3] = v3;
        }
    }
}

// ---------------- CSR gather-aggregation: dst[i] += sum_{j in N(i)} src[j] ----------------
// half-warp (16 lanes, float4 each) per dst node; no atomics.
__global__ __launch_bounds__(256) void k_agg(const float* __restrict__ src,
                                             float* __restrict__ dst, int M) {
    int node = blockIdx.x * 16 + (threadIdx.x >> 4);
    int l16  = threadIdx.x & 15;
    if (node >= M) return;
    int beg = g_ptr[node], end = g_ptr[node + 1];

    float4 acc = *(const float4*)(dst + (size_t)node * DOUT + l16 * 4);

    int e = beg;
    for (; e + 2 <= end; e += 2) {
        int s0 = g_csr[e], s1 = g_csr[e + 1];
        float4 v0 = *(const float4*)(src + (size_t)s0 * DOUT + l16 * 4);
        float4 v1 = *(const float4*)(src + (size_t)s1 * DOUT + l16 * 4);
        acc.x += v0.x + v1.x; acc.y += v0.y + v1.y;
        acc.z += v0.z + v1.z; acc.w += v0.w + v1.w;
    }
    if (e < end) {
        int s0 = g_csr[e];
        float4 v0 = *(const float4*)(src + (size_t)s0 * DOUT + l16 * 4);
        acc.x += v0.x; acc.y += v0.y; acc.z += v0.z; acc.w += v0.w;
    }
    *(float4*)(dst + (size_t)node * DOUT + l16 * 4) = acc;
}

// ---------------- host orchestration ----------------
extern "C" void kernel_launch(void* const* d_in, const int* in_sizes, int n_in,
                              void* d_out, int out_size)
{
    const float* x      = (const float*)d_in[0];
    const int*   ei32   = (const int*)d_in[1];
    const float* W_rel  = (const float*)d_in[2];
    const float* b_rel  = (const float*)d_in[3];
    const float* W_root = (const float*)d_in[4];
    const float* fc_w   = (const float*)d_in[5];
    const float* fc_b   = (const float*)d_in[6];
    float*       out    = (float*)d_out;

    int M  = in_sizes[0] / D;
    int nE = in_sizes[1] / 2;
    int L  = in_sizes[2] / (D * D);
    if (M > NN_MAX) M = NN_MAX;
    if (nE > NE_MAX) nE = NE_MAX;
    if (L > L_MAX) L = L_MAX;

    float *Ma, *Mb, *bA, *bB, *Vbase, *d1, *d2;
    cudaGetSymbolAddress((void**)&Ma, g_Ma);
    cudaGetSymbolAddress((void**)&Mb, g_Mb);
    cudaGetSymbolAddress((void**)&bA, g_bA);
    cudaGetSymbolAddress((void**)&bB, g_bB);
    cudaGetSymbolAddress((void**)&Vbase, g_V);
    cudaGetSymbolAddress((void**)&d1, g_d1);
    cudaGetSymbolAddress((void**)&d2, g_d2);

    // edges -> CSR
    k_detect<<<1, 256>>>(ei32, in_sizes[1]);
    k_zero_cnt<<<(M + 255) / 256, 256>>>(M);
    k_prep_edges<<<(nE + 255) / 256, 256>>>(ei32, nE, M);
    int nB = (M + SCAN_BLK - 1) / SCAN_BLK;
    k_scan1<<<nB, SCAN_BLK>>>(M);
    k_scan2<<<1, 128>>>(nB);
    k_scan3<<<(M + 255) / 256, 256>>>(M, nE);
    k_fill<<<(nE + 255) / 256, 256>>>(nE);
    k_d2<<<(M + 255) / 256, 256>>>(M);

    // weight recurrence (tiny, smem-tiled)
    k_init_M<<<(KMAX * D * D + KMAX * D + 255) / 256, 256>>>();
    const float* Min = Ma;  float* Mout = Mb;
    const float* bin = bA;  float* bout = bB;
    for (int l = 1; l <= L; ++l) {
        const float* Wr = W_rel  + (size_t)(l - 1) * D * D;
        const float* Wt = W_root + (size_t)(l - 1) * D * D;
        const float* bl = b_rel  + (size_t)(l - 1) * D;
        k_stage<<<dim3(8, l + 1), 256>>>(Min, Mout, Wr, Wt, l);
        k_stage_beta<<<1, 128>>>(bin, bout, Wr, Wt, bl, l);
        const float* t1 = Min; Min = Mout; Mout = (float*)t1;
        const float* t2 = bin; bin = bout; bout = (float*)t2;
    }
    k_make_C<<<dim3(4, L + 1), 256>>>(Min, fc_w);
    k_make_gamma<<<1, 64>>>(bin, fc_w, fc_b, L);

    // V_k = x0 @ C_k   (k=0 -> out with bias/degree epilogue)
    int gemm_blocks = (M + 127) / 128;
    k_gemm_proj<<<dim3(gemm_blocks, L + 1), 256>>>(x, d1, d2, out, M);

    // Horner: out = V0 + A(V1 + A(V2 + A V3)), CSR gather (no atomics)
    int agg_blocks = (M + 15) / 16;
    for (int k = L; k >= 1; --k) {
        const float* s = Vbase + (size_t)(k - 1) * NN_MAX * DOUT;
        float*       t = (k == 1) ? out : (Vbase + (size_t)(k - 2) * NN_MAX * DOUT);
        k_agg<<<agg_blocks, 256>>>(s, t, M);
    }
}